// round 1
// baseline (speedup 1.0000x reference)
#include <cuda_runtime.h>
#include <math.h>

// Problem constants
#define NB 2
#define NS 4096
#define DM 512
#define NH 8
#define DH 64
#define MTOT (NB * NS)   // 8192

// Scratch (device globals: allocation-free rule)
__device__ float g_q[NB * NH * NS * DH];
__device__ float g_k[NB * NH * NS * DH];
__device__ float g_v[NB * NH * NS * DH];
__device__ float g_attn[MTOT * DM];

// ---------------------------------------------------------------------------
// Tiled fp32 GEMM body: C[64x64] tile, K-step 16, 256 threads, 4x4 per thread.
// x: [M,512] row-major, w: [512,512] row-major, bias: [512].
// scatter=true  -> write [B,H,S,dh] head layout (for Q/K/V projections)
// scatter=false -> write [M,512] row-major (for output projection)
// ---------------------------------------------------------------------------
__device__ __forceinline__ void gemm_body(const float* __restrict__ x,
                                          const float* __restrict__ w,
                                          const float* __restrict__ bias,
                                          float* __restrict__ out,
                                          bool scatter)
{
    __shared__ float As[16][66];   // A tile transposed: As[k][m], pad 66 -> conflict-free
    __shared__ float Bs[16][64];   // B tile: Bs[k][n]

    const int t  = threadIdx.x;
    const int tx = t & 15, ty = t >> 4;
    const int m0 = blockIdx.y * 64;
    const int n0 = blockIdx.x * 64;

    const int kA = t & 15, mA = t >> 4;   // A loader: 16k x 16m per pass, 4 passes
    const int nB = t & 63, kB = t >> 6;   // B loader: 4k x 64n per pass, 4 passes

    float acc[4][4];
#pragma unroll
    for (int r = 0; r < 4; r++)
#pragma unroll
        for (int c = 0; c < 4; c++) acc[r][c] = 0.f;

    for (int k0 = 0; k0 < DM; k0 += 16) {
#pragma unroll
        for (int p = 0; p < 4; p++)
            As[kA][mA + 16 * p] = x[(size_t)(m0 + mA + 16 * p) * DM + k0 + kA];
#pragma unroll
        for (int p = 0; p < 4; p++)
            Bs[kB + 4 * p][nB] = w[(size_t)(k0 + kB + 4 * p) * DM + n0 + nB];
        __syncthreads();

#pragma unroll
        for (int kk = 0; kk < 16; kk++) {
            float a[4];
#pragma unroll
            for (int r = 0; r < 4; r++) a[r] = As[kk][ty * 4 + r];
            float4 b4 = *(const float4*)&Bs[kk][tx * 4];
            float b[4] = {b4.x, b4.y, b4.z, b4.w};
#pragma unroll
            for (int r = 0; r < 4; r++)
#pragma unroll
                for (int c = 0; c < 4; c++)
                    acc[r][c] = fmaf(a[r], b[c], acc[r][c]);
        }
        __syncthreads();
    }

#pragma unroll
    for (int r = 0; r < 4; r++) {
        int m = m0 + ty * 4 + r;
#pragma unroll
        for (int c = 0; c < 4; c++) {
            int n = n0 + tx * 4 + c;
            float v = acc[r][c] + bias[n];
            if (scatter) {
                int b = m >> 12;            // m / 4096
                int s = m & (NS - 1);
                int h = n >> 6;             // n / 64
                int d = n & 63;
                out[((size_t)(b * NH + h) * NS + s) * DH + d] = v;
            } else {
                out[(size_t)m * DM + n] = v;
            }
        }
    }
}

__global__ __launch_bounds__(256) void qkv_proj_kernel(
    const float* __restrict__ q, const float* __restrict__ k, const float* __restrict__ v,
    const float* __restrict__ wq, const float* __restrict__ bq,
    const float* __restrict__ wk, const float* __restrict__ bk,
    const float* __restrict__ wv, const float* __restrict__ bv)
{
    const float *x, *w, *bias;
    float* out;
    if (blockIdx.z == 0)      { x = q; w = wq; bias = bq; out = g_q; }
    else if (blockIdx.z == 1) { x = k; w = wk; bias = bk; out = g_k; }
    else                      { x = v; w = wv; bias = bv; out = g_v; }
    gemm_body(x, w, bias, out, true);
}

__global__ __launch_bounds__(256) void out_proj_kernel(
    const float* __restrict__ wo, const float* __restrict__ bo, float* __restrict__ out)
{
    gemm_body(g_attn, wo, bo, out, false);
}

// ---------------------------------------------------------------------------
// Flash-style attention. One block per (bh, 64-query tile). 256 threads.
// Smem: Qs[64][64], KP[64][65] (K-tile and P-tile share, time-multiplexed),
// Vs[64][64]. O accumulated in registers with online softmax.
// ---------------------------------------------------------------------------
__global__ __launch_bounds__(256, 3) void attn_kernel()
{
    extern __shared__ float sm[];
    float* Qs = sm;                 // 64*64
    float* KP = sm + 64 * 64;       // 64*65 (union: K tile, then P tile)
    float* Vs = KP + 64 * 65;       // 64*64

    const int t  = threadIdx.x;
    const int tx = t & 15, ty = t >> 4;
    const int bh = blockIdx.y;
    const int q0 = blockIdx.x * 64;

    const float* Qg = g_q + (size_t)bh * NS * DH;
    const float* Kg = g_k + (size_t)bh * NS * DH;
    const float* Vg = g_v + (size_t)bh * NS * DH;

    // Load Q tile, pre-scaled by 1/sqrt(dh)
    {
        int d = t & 63, i0 = t >> 6;
#pragma unroll
        for (int p = 0; p < 16; p++) {
            int i = i0 + 4 * p;
            Qs[i * 64 + d] = Qg[(size_t)(q0 + i) * DH + d] * 0.125f;
        }
    }

    float o[4][4], mi[4], li[4];
#pragma unroll
    for (int r = 0; r < 4; r++) {
        mi[r] = -1e30f; li[r] = 0.f;
#pragma unroll
        for (int c = 0; c < 4; c++) o[r][c] = 0.f;
    }

    for (int kt = 0; kt < NS / 64; kt++) {
        const int k0 = kt * 64;
        {   // load K (into KP) and V tiles; conflict-free writes, coalesced reads
            int d = t & 63, j0 = t >> 6;
#pragma unroll
            for (int p = 0; p < 16; p++) {
                int j = j0 + 4 * p;
                KP[j * 65 + d] = Kg[(size_t)(k0 + j) * DH + d];
                Vs[j * 64 + d] = Vg[(size_t)(k0 + j) * DH + d];
            }
        }
        __syncthreads();   // also covers Q-tile store on first iteration

        // S = Q @ K^T  (64x64x64)
        float s[4][4];
#pragma unroll
        for (int r = 0; r < 4; r++)
#pragma unroll
            for (int c = 0; c < 4; c++) s[r][c] = 0.f;

#pragma unroll 4
        for (int d = 0; d < 64; d++) {
            float a[4], b[4];
#pragma unroll
            for (int r = 0; r < 4; r++) a[r] = Qs[(ty * 4 + r) * 64 + d];
#pragma unroll
            for (int c = 0; c < 4; c++) b[c] = KP[(tx * 4 + c) * 65 + d];
#pragma unroll
            for (int r = 0; r < 4; r++)
#pragma unroll
                for (int c = 0; c < 4; c++)
                    s[r][c] = fmaf(a[r], b[c], s[r][c]);
        }
        __syncthreads();   // done reading K tile; region becomes P tile

        // Online softmax: row-stat reduction across the 16 lanes (tx) of each row.
#pragma unroll
        for (int r = 0; r < 4; r++) {
            float mx = fmaxf(fmaxf(s[r][0], s[r][1]), fmaxf(s[r][2], s[r][3]));
#pragma unroll
            for (int off = 8; off; off >>= 1)
                mx = fmaxf(mx, __shfl_xor_sync(0xffffffffu, mx, off));
            float mnew = fmaxf(mi[r], mx);
            float corr = __expf(mi[r] - mnew);
            mi[r] = mnew;
            float rs = 0.f;
#pragma unroll
            for (int c = 0; c < 4; c++) {
                s[r][c] = __expf(s[r][c] - mnew);
                rs += s[r][c];
            }
#pragma unroll
            for (int off = 8; off; off >>= 1)
                rs += __shfl_xor_sync(0xffffffffu, rs, off);
            li[r] = li[r] * corr + rs;
#pragma unroll
            for (int c = 0; c < 4; c++) o[r][c] *= corr;
        }

        // Write P tile
#pragma unroll
        for (int r = 0; r < 4; r++)
#pragma unroll
            for (int c = 0; c < 4; c++)
                KP[(ty * 4 + r) * 65 + tx * 4 + c] = s[r][c];
        __syncthreads();

        // O += P @ V  (64x64x64)
#pragma unroll 4
        for (int j = 0; j < 64; j++) {
            float a[4];
#pragma unroll
            for (int r = 0; r < 4; r++) a[r] = KP[(ty * 4 + r) * 65 + j];
            float4 v4 = *(const float4*)&Vs[j * 64 + tx * 4];
#pragma unroll
            for (int r = 0; r < 4; r++) {
                o[r][0] = fmaf(a[r], v4.x, o[r][0]);
                o[r][1] = fmaf(a[r], v4.y, o[r][1]);
                o[r][2] = fmaf(a[r], v4.z, o[r][2]);
                o[r][3] = fmaf(a[r], v4.w, o[r][3]);
            }
        }
        __syncthreads();   // safe to overwrite P/V next iteration
    }

    // Epilogue: normalize and store combined [B,S,D] layout
    const int b = bh >> 3, h = bh & 7;
#pragma unroll
    for (int r = 0; r < 4; r++) {
        float inv = 1.f / li[r];
        int srow = q0 + ty * 4 + r;
#pragma unroll
        for (int c = 0; c < 4; c++)
            g_attn[((size_t)(b * NS + srow)) * DM + h * DH + tx * 4 + c] = o[r][c] * inv;
    }
}

// ---------------------------------------------------------------------------
extern "C" void kernel_launch(void* const* d_in, const int* in_sizes, int n_in,
                              void* d_out, int out_size)
{
    const float* q  = (const float*)d_in[0];
    const float* k  = (const float*)d_in[1];
    const float* v  = (const float*)d_in[2];
    const float* wq = (const float*)d_in[3];
    const float* bq = (const float*)d_in[4];
    const float* wk = (const float*)d_in[5];
    const float* bk = (const float*)d_in[6];
    const float* wv = (const float*)d_in[7];
    const float* bv = (const float*)d_in[8];
    const float* wo = (const float*)d_in[9];
    const float* bo = (const float*)d_in[10];
    float* out = (float*)d_out;

    const int smem = (64 * 64 + 64 * 65 + 64 * 64) * (int)sizeof(float);  // 49408 B
    cudaFuncSetAttribute(attn_kernel, cudaFuncAttributeMaxDynamicSharedMemorySize, smem);

    dim3 blk(256);
    qkv_proj_kernel<<<dim3(DM / 64, MTOT / 64, 3), blk>>>(q, k, v, wq, bq, wk, bk, wv, bv);
    attn_kernel<<<dim3(NS / 64, NB * NH), blk, smem>>>();
    out_proj_kernel<<<dim3(DM / 64, MTOT / 64), blk>>>(wo, bo, out);
}

// round 2
// speedup vs baseline: 2.5620x; 2.5620x over previous
#include <cuda_runtime.h>
#include <cuda_bf16.h>
#include <stdint.h>
#include <math.h>

#define NB 2
#define NS 4096
#define DM 512
#define NH 8
#define DH 64
#define MTOT (NB * NS)          // 8192
#define MK   (MTOT * DM)        // 4194304

// ---------------------------------------------------------------------------
// Device-global scratch (allocation-free rule). All bf16 hi/lo split pairs.
// ---------------------------------------------------------------------------
__device__ __align__(256) __nv_bfloat16 g_x_hi[3 * MK], g_x_lo[3 * MK];      // split q/k/v inputs [z][m][k]
__device__ __align__(256) __nv_bfloat16 g_w_hi[4 * DM * DM], g_w_lo[4 * DM * DM]; // wT [z][n][k]
__device__ __align__(256) __nv_bfloat16 g_q_hi[MK], g_q_lo[MK];              // [bh][s][dh], pre-scaled by 0.125
__device__ __align__(256) __nv_bfloat16 g_k_hi[MK], g_k_lo[MK];              // [bh][s][dh]
__device__ __align__(256) __nv_bfloat16 g_v_hi[MK], g_v_lo[MK];              // [bh][s][dh]
__device__ __align__(256) __nv_bfloat16 g_a_hi[MK], g_a_lo[MK];              // attn out [s][dm]

// ---------------------------------------------------------------------------
// PTX helpers
// ---------------------------------------------------------------------------
__device__ __forceinline__ void mma_bf16(float* c, uint32_t a0, uint32_t a1,
                                         uint32_t a2, uint32_t a3,
                                         uint32_t b0, uint32_t b1) {
    asm volatile(
        "mma.sync.aligned.m16n8k16.row.col.f32.bf16.bf16.f32 "
        "{%0,%1,%2,%3},{%4,%5,%6,%7},{%8,%9},{%0,%1,%2,%3};"
        : "+f"(c[0]), "+f"(c[1]), "+f"(c[2]), "+f"(c[3])
        : "r"(a0), "r"(a1), "r"(a2), "r"(a3), "r"(b0), "r"(b1));
}

__device__ __forceinline__ void ldm4t(uint32_t* r, uint32_t addr) {
    asm volatile(
        "ldmatrix.sync.aligned.m8n8.x4.trans.shared.b16 {%0,%1,%2,%3},[%4];"
        : "=r"(r[0]), "=r"(r[1]), "=r"(r[2]), "=r"(r[3]) : "r"(addr));
}

__device__ __forceinline__ void cpa16(uint32_t dst, const void* src) {
    asm volatile("cp.async.cg.shared.global [%0], [%1], 16;\n" :: "r"(dst), "l"(src));
}
__device__ __forceinline__ void cp_commit() { asm volatile("cp.async.commit_group;\n"); }
__device__ __forceinline__ void cp_wait0() { asm volatile("cp.async.wait_group 0;\n"); }
__device__ __forceinline__ void cp_wait1() { asm volatile("cp.async.wait_group 1;\n"); }

__device__ __forceinline__ uint32_t ld32(const __nv_bfloat16* p) {
    return *(const uint32_t*)p;
}

// split x into bf16 hi + bf16 lo (2-term compensated decomposition)
__device__ __forceinline__ void split1(float x, __nv_bfloat16& h, __nv_bfloat16& l) {
    h = __float2bfloat16(x);
    l = __float2bfloat16(x - __bfloat162float(h));
}
// split a pair and pack into bf16x2 u32 (element0 in low half)
__device__ __forceinline__ void split_pack(float e0, float e1, uint32_t& hi, uint32_t& lo) {
    __nv_bfloat16 h0, l0, h1, l1;
    split1(e0, h0, l0);
    split1(e1, h1, l1);
    hi = (uint32_t)*(unsigned short*)&h0 | ((uint32_t)*(unsigned short*)&h1 << 16);
    lo = (uint32_t)*(unsigned short*)&l0 | ((uint32_t)*(unsigned short*)&l1 << 16);
}

// ---------------------------------------------------------------------------
// Weight transpose + split: w[k][n] fp32 -> wT_hi/lo[n][k] bf16
// ---------------------------------------------------------------------------
__global__ void wsplit_kernel(const float* __restrict__ wq, const float* __restrict__ wk,
                              const float* __restrict__ wv, const float* __restrict__ wo) {
    __shared__ float tl[32][33];
    const float* w = blockIdx.z == 0 ? wq : blockIdx.z == 1 ? wk : blockIdx.z == 2 ? wv : wo;
    const int n0 = blockIdx.x * 32, k0 = blockIdx.y * 32;
    const int tx = threadIdx.x, ty = threadIdx.y;  // 32 x 8
#pragma unroll
    for (int i = 0; i < 32; i += 8)
        tl[ty + i][tx] = w[(size_t)(k0 + ty + i) * DM + n0 + tx];
    __syncthreads();
#pragma unroll
    for (int i = 0; i < 32; i += 8) {
        float v = tl[tx][ty + i];
        __nv_bfloat16 h, l;
        split1(v, h, l);
        size_t idx = (size_t)blockIdx.z * DM * DM + (size_t)(n0 + ty + i) * DM + k0 + tx;
        g_w_hi[idx] = h;
        g_w_lo[idx] = l;
    }
}

// ---------------------------------------------------------------------------
// Input split: q/k/v fp32 [m][k] -> g_x_hi/lo
// ---------------------------------------------------------------------------
__global__ void xsplit_kernel(const float* __restrict__ q, const float* __restrict__ k,
                              const float* __restrict__ v) {
    const int z = blockIdx.y;
    const float* src = z == 0 ? q : z == 1 ? k : v;
    int i = blockIdx.x * 256 + threadIdx.x;
    float x = src[i];
    __nv_bfloat16 h, l;
    split1(x, h, l);
    g_x_hi[(size_t)z * MK + i] = h;
    g_x_lo[(size_t)z * MK + i] = l;
}

// ---------------------------------------------------------------------------
// bf16 3-term GEMM core: C[128x128] block, 8 warps (2m x 4n), warp 64m x 32n.
// A [M][512] row-major bf16 (hi/lo), B = wT [N][512] row-major bf16 (hi/lo).
// mode 0: scatter-split epilogue into q/k/v head layout (z picks dest).
// mode 1: fp32 epilogue into outF.
// smem: 2 bufs x {Ah,Al,Bh,Bl} x 128 rows x pitch 40 bf16.
// ---------------------------------------------------------------------------
__device__ __forceinline__ void gemm_core(const __nv_bfloat16* __restrict__ aH,
                                          const __nv_bfloat16* __restrict__ aL,
                                          const __nv_bfloat16* __restrict__ wH,
                                          const __nv_bfloat16* __restrict__ wL,
                                          const float* __restrict__ bias,
                                          int mode, int z, float* __restrict__ outF) {
    extern __shared__ __nv_bfloat16 sb[];
    const int t = threadIdx.x, lane = t & 31, warp = t >> 5;
    const int g = lane >> 2, c4 = lane & 3;
    const int wm = warp >> 2, wn = warp & 3;
    const int m0 = blockIdx.y * 128, n0 = blockIdx.x * 128;
    const uint32_t smem_u32 = (uint32_t)__cvta_generic_to_shared(sb);

    const __nv_bfloat16* ptrs[4] = { aH + (size_t)m0 * DM, aL + (size_t)m0 * DM,
                                     wH + (size_t)n0 * DM, wL + (size_t)n0 * DM };

    float c[4][4][4];
#pragma unroll
    for (int a = 0; a < 4; a++)
#pragma unroll
        for (int b = 0; b < 4; b++)
#pragma unroll
            for (int e = 0; e < 4; e++) c[a][b][e] = 0.f;

    auto issue = [&](int buf, int kc0) {
#pragma unroll
        for (int arr = 0; arr < 4; arr++)
#pragma unroll
            for (int i = 0; i < 2; i++) {
                int ch = t * 2 + i;          // 0..511
                int row = ch >> 2, seg = ch & 3;
                const void* src = ptrs[arr] + (size_t)row * DM + kc0 + seg * 8;
                uint32_t dst = smem_u32 + ((buf * 4 + arr) * 5120 + row * 40 + seg * 8) * 2;
                cpa16(dst, src);
            }
    };

    issue(0, 0);
    cp_commit();

    for (int it = 0; it < 16; ++it) {
        if (it < 15) { issue((it + 1) & 1, (it + 1) * 32); cp_commit(); cp_wait1(); }
        else cp_wait0();
        __syncthreads();

        const __nv_bfloat16* Ah = sb + ((it & 1) * 4 + 0) * 5120;
        const __nv_bfloat16* Al = sb + ((it & 1) * 4 + 1) * 5120;
        const __nv_bfloat16* Bh = sb + ((it & 1) * 4 + 2) * 5120;
        const __nv_bfloat16* Bl = sb + ((it & 1) * 4 + 3) * 5120;

#pragma unroll
        for (int ks = 0; ks < 2; ++ks) {
            uint32_t ah[4][4], al[4][4];
#pragma unroll
            for (int mt = 0; mt < 4; ++mt) {
                int r0 = wm * 64 + mt * 16 + g;
                const __nv_bfloat16* p = Ah + r0 * 40 + ks * 16 + c4 * 2;
                ah[mt][0] = ld32(p);
                ah[mt][1] = ld32(p + 8 * 40);
                ah[mt][2] = ld32(p + 8);
                ah[mt][3] = ld32(p + 8 * 40 + 8);
                const __nv_bfloat16* q = Al + r0 * 40 + ks * 16 + c4 * 2;
                al[mt][0] = ld32(q);
                al[mt][1] = ld32(q + 8 * 40);
                al[mt][2] = ld32(q + 8);
                al[mt][3] = ld32(q + 8 * 40 + 8);
            }
#pragma unroll
            for (int nt = 0; nt < 4; ++nt) {
                int rn = wn * 32 + nt * 8 + g;
                const __nv_bfloat16* pb = Bh + rn * 40 + ks * 16 + c4 * 2;
                uint32_t b0h = ld32(pb), b1h = ld32(pb + 8);
                const __nv_bfloat16* pl = Bl + rn * 40 + ks * 16 + c4 * 2;
                uint32_t b0l = ld32(pl), b1l = ld32(pl + 8);
#pragma unroll
                for (int mt = 0; mt < 4; ++mt) {
                    mma_bf16(c[mt][nt], ah[mt][0], ah[mt][1], ah[mt][2], ah[mt][3], b0h, b1h);
                    mma_bf16(c[mt][nt], ah[mt][0], ah[mt][1], ah[mt][2], ah[mt][3], b0l, b1l);
                    mma_bf16(c[mt][nt], al[mt][0], al[mt][1], al[mt][2], al[mt][3], b0h, b1h);
                }
            }
        }
        __syncthreads();
    }

    // epilogue
    __nv_bfloat16* dh = z == 0 ? g_q_hi : z == 1 ? g_k_hi : g_v_hi;
    __nv_bfloat16* dl = z == 0 ? g_q_lo : z == 1 ? g_k_lo : g_v_lo;
#pragma unroll
    for (int mt = 0; mt < 4; ++mt) {
        int mA = m0 + wm * 64 + mt * 16 + g;
#pragma unroll
        for (int nt = 0; nt < 4; ++nt) {
            int n = n0 + wn * 32 + nt * 8 + c4 * 2;
            float b0 = bias[n], b1 = bias[n + 1];
            float v00 = c[mt][nt][0] + b0, v01 = c[mt][nt][1] + b1;
            float v10 = c[mt][nt][2] + b0, v11 = c[mt][nt][3] + b1;
            if (mode == 0) {
                if (z == 0) { v00 *= 0.125f; v01 *= 0.125f; v10 *= 0.125f; v11 *= 0.125f; }
                int b_ = mA >> 12, s_ = mA & (NS - 1), h_ = n >> 6, d_ = n & 63;
                size_t idx = ((size_t)(b_ * NH + h_) * NS + s_) * DH + d_;
                uint32_t hi, lo;
                split_pack(v00, v01, hi, lo);
                *(uint32_t*)&dh[idx] = hi;
                *(uint32_t*)&dl[idx] = lo;
                split_pack(v10, v11, hi, lo);
                *(uint32_t*)&dh[idx + 8 * DH] = hi;
                *(uint32_t*)&dl[idx + 8 * DH] = lo;
            } else {
                outF[(size_t)mA * DM + n] = v00;
                outF[(size_t)mA * DM + n + 1] = v01;
                outF[(size_t)(mA + 8) * DM + n] = v10;
                outF[(size_t)(mA + 8) * DM + n + 1] = v11;
            }
        }
    }
}

__global__ __launch_bounds__(256) void gemm_qkv_kernel(const float* __restrict__ bq,
                                                       const float* __restrict__ bk,
                                                       const float* __restrict__ bv) {
    const int z = blockIdx.z;
    const float* bias = z == 0 ? bq : z == 1 ? bk : bv;
    gemm_core(g_x_hi + (size_t)z * MK, g_x_lo + (size_t)z * MK,
              g_w_hi + (size_t)z * DM * DM, g_w_lo + (size_t)z * DM * DM,
              bias, 0, z, nullptr);
}

__global__ __launch_bounds__(256) void gemm_out_kernel(const float* __restrict__ bo,
                                                       float* __restrict__ out) {
    gemm_core(g_a_hi, g_a_lo, g_w_hi + (size_t)3 * DM * DM, g_w_lo + (size_t)3 * DM * DM,
              bo, 1, 0, out);
}

// ---------------------------------------------------------------------------
// Flash attention, bf16 3-term mma. Q tile 128 (8 warps x 16 rows), K tile 64.
// Q fragments live in registers for the whole pass. P reused as A fragments
// directly (C-frag layout == A-frag layout). V via ldmatrix.x4.trans.
// smem: 2 bufs x {Kh,Kl,Vh,Vl} x 64 rows x pitch 72 bf16 = 73728 B.
// ---------------------------------------------------------------------------
__global__ __launch_bounds__(256) void attn_kernel() {
    extern __shared__ __nv_bfloat16 sb[];
    const int t = threadIdx.x, lane = t & 31, warp = t >> 5;
    const int g = lane >> 2, c4 = lane & 3;
    const int bh = blockIdx.y;
    const int qr = blockIdx.x * 128 + warp * 16;
    const uint32_t smem_u32 = (uint32_t)__cvta_generic_to_shared(sb);
    const size_t bho = (size_t)bh * NS * DH;

    const __nv_bfloat16* srcs[4] = { g_k_hi + bho, g_k_lo + bho, g_v_hi + bho, g_v_lo + bho };

    // load Q fragments (rows qr+g / qr+g+8, 4 k-steps of 16)
    uint32_t qh[4][4], ql[4][4];
    {
        const __nv_bfloat16* Qh = g_q_hi + bho;
        const __nv_bfloat16* Ql = g_q_lo + bho;
#pragma unroll
        for (int ks = 0; ks < 4; ++ks) {
            const __nv_bfloat16* p = Qh + (size_t)(qr + g) * DH + ks * 16 + c4 * 2;
            qh[ks][0] = ld32(p);
            qh[ks][1] = ld32(p + 8 * DH);
            qh[ks][2] = ld32(p + 8);
            qh[ks][3] = ld32(p + 8 * DH + 8);
            const __nv_bfloat16* q = Ql + (size_t)(qr + g) * DH + ks * 16 + c4 * 2;
            ql[ks][0] = ld32(q);
            ql[ks][1] = ld32(q + 8 * DH);
            ql[ks][2] = ld32(q + 8);
            ql[ks][3] = ld32(q + 8 * DH + 8);
        }
    }

    float o[8][4];
#pragma unroll
    for (int i = 0; i < 8; i++)
#pragma unroll
        for (int e = 0; e < 4; e++) o[i][e] = 0.f;
    float m0 = -1e30f, m1 = -1e30f, l0 = 0.f, l1 = 0.f;

    auto issue = [&](int buf, int kt) {
        const int k0 = kt * 64;
#pragma unroll
        for (int arr = 0; arr < 4; arr++)
#pragma unroll
            for (int i = 0; i < 2; i++) {
                int ch = t * 2 + i;          // 0..511
                int row = ch >> 3, seg = ch & 7;
                const void* src = srcs[arr] + (size_t)(k0 + row) * DH + seg * 8;
                uint32_t dst = smem_u32 + ((buf * 4 + arr) * 4608 + row * 72 + seg * 8) * 2;
                cpa16(dst, src);
            }
    };

    issue(0, 0);
    cp_commit();

    for (int kt = 0; kt < NS / 64; ++kt) {
        if (kt < NS / 64 - 1) { issue((kt + 1) & 1, kt + 1); cp_commit(); cp_wait1(); }
        else cp_wait0();
        __syncthreads();

        const int bb = kt & 1;
        const __nv_bfloat16* Kh = sb + (bb * 4 + 0) * 4608;
        const __nv_bfloat16* Kl = sb + (bb * 4 + 1) * 4608;
        const uint32_t vh_base = smem_u32 + (bb * 4 + 2) * 4608 * 2;
        const uint32_t vl_base = smem_u32 + (bb * 4 + 3) * 4608 * 2;

        // S = Q K^T
        float s[8][4];
#pragma unroll
        for (int i = 0; i < 8; i++)
#pragma unroll
            for (int e = 0; e < 4; e++) s[i][e] = 0.f;

#pragma unroll
        for (int ks = 0; ks < 4; ++ks)
#pragma unroll
            for (int nt = 0; nt < 8; ++nt) {
                int j = nt * 8 + g;
                const __nv_bfloat16* pb = Kh + j * 72 + ks * 16 + c4 * 2;
                uint32_t b0h = ld32(pb), b1h = ld32(pb + 8);
                const __nv_bfloat16* pl = Kl + j * 72 + ks * 16 + c4 * 2;
                uint32_t b0l = ld32(pl), b1l = ld32(pl + 8);
                mma_bf16(s[nt], qh[ks][0], qh[ks][1], qh[ks][2], qh[ks][3], b0h, b1h);
                mma_bf16(s[nt], qh[ks][0], qh[ks][1], qh[ks][2], qh[ks][3], b0l, b1l);
                mma_bf16(s[nt], ql[ks][0], ql[ks][1], ql[ks][2], ql[ks][3], b0h, b1h);
            }

        // online softmax (rows g and g+8)
        float mx0 = -1e30f, mx1 = -1e30f;
#pragma unroll
        for (int nt = 0; nt < 8; ++nt) {
            mx0 = fmaxf(mx0, fmaxf(s[nt][0], s[nt][1]));
            mx1 = fmaxf(mx1, fmaxf(s[nt][2], s[nt][3]));
        }
        mx0 = fmaxf(mx0, __shfl_xor_sync(0xffffffffu, mx0, 1));
        mx0 = fmaxf(mx0, __shfl_xor_sync(0xffffffffu, mx0, 2));
        mx1 = fmaxf(mx1, __shfl_xor_sync(0xffffffffu, mx1, 1));
        mx1 = fmaxf(mx1, __shfl_xor_sync(0xffffffffu, mx1, 2));
        float mn0 = fmaxf(m0, mx0), mn1 = fmaxf(m1, mx1);
        float cr0 = __expf(m0 - mn0), cr1 = __expf(m1 - mn1);
        m0 = mn0; m1 = mn1;
        float sum0 = 0.f, sum1 = 0.f;
#pragma unroll
        for (int nt = 0; nt < 8; ++nt) {
            s[nt][0] = __expf(s[nt][0] - mn0); sum0 += s[nt][0];
            s[nt][1] = __expf(s[nt][1] - mn0); sum0 += s[nt][1];
            s[nt][2] = __expf(s[nt][2] - mn1); sum1 += s[nt][2];
            s[nt][3] = __expf(s[nt][3] - mn1); sum1 += s[nt][3];
        }
        sum0 += __shfl_xor_sync(0xffffffffu, sum0, 1);
        sum0 += __shfl_xor_sync(0xffffffffu, sum0, 2);
        sum1 += __shfl_xor_sync(0xffffffffu, sum1, 1);
        sum1 += __shfl_xor_sync(0xffffffffu, sum1, 2);
        l0 = l0 * cr0 + sum0;
        l1 = l1 * cr1 + sum1;
#pragma unroll
        for (int nt = 0; nt < 8; ++nt) {
            o[nt][0] *= cr0; o[nt][1] *= cr0; o[nt][2] *= cr1; o[nt][3] *= cr1;
        }

        // O += P V   (P from s fragments, split on the fly)
#pragma unroll
        for (int tk = 0; tk < 4; ++tk) {
            uint32_t ah[4], al[4];
            split_pack(s[2 * tk][0],     s[2 * tk][1],     ah[0], al[0]);
            split_pack(s[2 * tk][2],     s[2 * tk][3],     ah[1], al[1]);
            split_pack(s[2 * tk + 1][0], s[2 * tk + 1][1], ah[2], al[2]);
            split_pack(s[2 * tk + 1][2], s[2 * tk + 1][3], ah[3], al[3]);
            int jrow = tk * 16 + (lane & 15);
            int coff = (lane >> 4) * 8;
#pragma unroll
            for (int np = 0; np < 4; ++np) {
                uint32_t vh[4], vl[4];
                ldm4t(vh, vh_base + (jrow * 72 + np * 16 + coff) * 2);
                ldm4t(vl, vl_base + (jrow * 72 + np * 16 + coff) * 2);
                mma_bf16(o[np * 2],     ah[0], ah[1], ah[2], ah[3], vh[0], vh[1]);
                mma_bf16(o[np * 2],     ah[0], ah[1], ah[2], ah[3], vl[0], vl[1]);
                mma_bf16(o[np * 2],     al[0], al[1], al[2], al[3], vh[0], vh[1]);
                mma_bf16(o[np * 2 + 1], ah[0], ah[1], ah[2], ah[3], vh[2], vh[3]);
                mma_bf16(o[np * 2 + 1], ah[0], ah[1], ah[2], ah[3], vl[2], vl[3]);
                mma_bf16(o[np * 2 + 1], al[0], al[1], al[2], al[3], vh[2], vh[3]);
            }
        }
        __syncthreads();
    }

    // epilogue: normalize, split, write [s][dm] bf16 hi/lo
    float inv0 = 1.f / l0, inv1 = 1.f / l1;
    const int b_ = bh >> 3, h_ = bh & 7;
    size_t r0 = (size_t)(b_ * NS + qr + g) * DM + h_ * 64;
    size_t r1 = r0 + (size_t)8 * DM;
#pragma unroll
    for (int nt = 0; nt < 8; ++nt) {
        uint32_t hi, lo;
        int d = nt * 8 + c4 * 2;
        split_pack(o[nt][0] * inv0, o[nt][1] * inv0, hi, lo);
        *(uint32_t*)&g_a_hi[r0 + d] = hi;
        *(uint32_t*)&g_a_lo[r0 + d] = lo;
        split_pack(o[nt][2] * inv1, o[nt][3] * inv1, hi, lo);
        *(uint32_t*)&g_a_hi[r1 + d] = hi;
        *(uint32_t*)&g_a_lo[r1 + d] = lo;
    }
}

// ---------------------------------------------------------------------------
extern "C" void kernel_launch(void* const* d_in, const int* in_sizes, int n_in,
                              void* d_out, int out_size) {
    const float* q  = (const float*)d_in[0];
    const float* k  = (const float*)d_in[1];
    const float* v  = (const float*)d_in[2];
    const float* wq = (const float*)d_in[3];
    const float* bq = (const float*)d_in[4];
    const float* wk = (const float*)d_in[5];
    const float* bk = (const float*)d_in[6];
    const float* wv = (const float*)d_in[7];
    const float* bv = (const float*)d_in[8];
    const float* wo = (const float*)d_in[9];
    const float* bo = (const float*)d_in[10];
    float* out = (float*)d_out;

    const int smem_gemm = 2 * 4 * 128 * 40 * 2;  // 81920
    const int smem_attn = 2 * 4 * 64 * 72 * 2;   // 73728
    cudaFuncSetAttribute(gemm_qkv_kernel, cudaFuncAttributeMaxDynamicSharedMemorySize, smem_gemm);
    cudaFuncSetAttribute(gemm_out_kernel, cudaFuncAttributeMaxDynamicSharedMemorySize, smem_gemm);
    cudaFuncSetAttribute(attn_kernel,     cudaFuncAttributeMaxDynamicSharedMemorySize, smem_attn);

    wsplit_kernel<<<dim3(16, 16, 4), dim3(32, 8)>>>(wq, wk, wv, wo);
    xsplit_kernel<<<dim3(MK / 256, 3), 256>>>(q, k, v);
    gemm_qkv_kernel<<<dim3(4, 64, 3), 256, smem_gemm>>>(bq, bk, bv);
    attn_kernel<<<dim3(32, 16), 256, smem_attn>>>();
    gemm_out_kernel<<<dim3(4, 64), 256, smem_gemm>>>(bo, out);
}

// round 4
// speedup vs baseline: 2.7634x; 1.0786x over previous
#include <cuda_runtime.h>
#include <cuda_bf16.h>
#include <stdint.h>
#include <math.h>

#define NB 2
#define NS 4096
#define DM 512
#define NH 8
#define DH 64
#define MTOT (NB * NS)          // 8192
#define MK   (MTOT * DM)        // 4194304

// ---------------------------------------------------------------------------
// Device-global scratch. bf16 hi/lo split pairs.
// ---------------------------------------------------------------------------
__device__ __align__(256) __nv_bfloat16 g_x_hi[3 * MK], g_x_lo[3 * MK];           // split q/k/v inputs
__device__ __align__(256) __nv_bfloat16 g_w_hi[4 * DM * DM], g_w_lo[4 * DM * DM]; // wT [z][n][k]
__device__ __align__(256) __nv_bfloat16 g_q_hi[MK], g_q_lo[MK];                   // [bh][s][dh], pre-scaled 0.125
__device__ __align__(256) __nv_bfloat16 g_k_hi[MK], g_k_lo[MK];                   // [bh][s][dh]
__device__ __align__(256) __nv_bfloat16 g_v_hi[MK], g_v_lo[MK];                   // [bh][s][dh]
__device__ __align__(256) __nv_bfloat16 g_a_hi[MK], g_a_lo[MK];                   // attn out [s][dm]

// ---------------------------------------------------------------------------
// PTX helpers
// ---------------------------------------------------------------------------
__device__ __forceinline__ void mma_bf16(float* c, uint32_t a0, uint32_t a1,
                                         uint32_t a2, uint32_t a3,
                                         uint32_t b0, uint32_t b1) {
    asm volatile(
        "mma.sync.aligned.m16n8k16.row.col.f32.bf16.bf16.f32 "
        "{%0,%1,%2,%3},{%4,%5,%6,%7},{%8,%9},{%0,%1,%2,%3};"
        : "+f"(c[0]), "+f"(c[1]), "+f"(c[2]), "+f"(c[3])
        : "r"(a0), "r"(a1), "r"(a2), "r"(a3), "r"(b0), "r"(b1));
}

__device__ __forceinline__ void ldm4t(uint32_t* r, uint32_t addr) {
    asm volatile(
        "ldmatrix.sync.aligned.m8n8.x4.trans.shared.b16 {%0,%1,%2,%3},[%4];"
        : "=r"(r[0]), "=r"(r[1]), "=r"(r[2]), "=r"(r[3]) : "r"(addr));
}

__device__ __forceinline__ void cpa16(uint32_t dst, const void* src) {
    asm volatile("cp.async.cg.shared.global [%0], [%1], 16;\n" :: "r"(dst), "l"(src));
}
__device__ __forceinline__ void cp_commit() { asm volatile("cp.async.commit_group;\n"); }
__device__ __forceinline__ void cp_wait0() { asm volatile("cp.async.wait_group 0;\n"); }
__device__ __forceinline__ void cp_wait1() { asm volatile("cp.async.wait_group 1;\n"); }

__device__ __forceinline__ uint32_t ld32(const __nv_bfloat16* p) {
    return *(const uint32_t*)p;
}

// split x into bf16 hi + bf16 lo (2-term compensated decomposition)
__device__ __forceinline__ void split1(float x, __nv_bfloat16& h, __nv_bfloat16& l) {
    h = __float2bfloat16(x);
    l = __float2bfloat16(x - __bfloat162float(h));
}
__device__ __forceinline__ void split_pack(float e0, float e1, uint32_t& hi, uint32_t& lo) {
    __nv_bfloat16 h0, l0, h1, l1;
    split1(e0, h0, l0);
    split1(e1, h1, l1);
    hi = (uint32_t)*(unsigned short*)&h0 | ((uint32_t)*(unsigned short*)&h1 << 16);
    lo = (uint32_t)*(unsigned short*)&l0 | ((uint32_t)*(unsigned short*)&l1 << 16);
}

// ---------------------------------------------------------------------------
// Weight transpose + split: w[k][n] fp32 -> wT_hi/lo[n][k] bf16
// ---------------------------------------------------------------------------
__global__ void wsplit_kernel(const float* __restrict__ wq, const float* __restrict__ wk,
                              const float* __restrict__ wv, const float* __restrict__ wo) {
    __shared__ float tl[32][33];
    const float* w = blockIdx.z == 0 ? wq : blockIdx.z == 1 ? wk : blockIdx.z == 2 ? wv : wo;
    const int n0 = blockIdx.x * 32, k0 = blockIdx.y * 32;
    const int tx = threadIdx.x, ty = threadIdx.y;  // 32 x 8
#pragma unroll
    for (int i = 0; i < 32; i += 8)
        tl[ty + i][tx] = w[(size_t)(k0 + ty + i) * DM + n0 + tx];
    __syncthreads();
#pragma unroll
    for (int i = 0; i < 32; i += 8) {
        float v = tl[tx][ty + i];
        __nv_bfloat16 h, l;
        split1(v, h, l);
        size_t idx = (size_t)blockIdx.z * DM * DM + (size_t)(n0 + ty + i) * DM + k0 + tx;
        g_w_hi[idx] = h;
        g_w_lo[idx] = l;
    }
}

// ---------------------------------------------------------------------------
// Input split: q/k/v fp32 [m][k] -> g_x_hi/lo, float4-vectorized
// ---------------------------------------------------------------------------
__global__ void xsplit_kernel(const float* __restrict__ q, const float* __restrict__ k,
                              const float* __restrict__ v) {
    const int z = blockIdx.y;
    const float* src = z == 0 ? q : z == 1 ? k : v;
    int i = (blockIdx.x * 256 + threadIdx.x) * 4;
    float4 x4 = *(const float4*)(src + i);
    uint32_t h01, l01, h23, l23;
    split_pack(x4.x, x4.y, h01, l01);
    split_pack(x4.z, x4.w, h23, l23);
    uint2 hh = make_uint2(h01, h23), ll = make_uint2(l01, l23);
    *(uint2*)&g_x_hi[(size_t)z * MK + i] = hh;
    *(uint2*)&g_x_lo[(size_t)z * MK + i] = ll;
}

// ---------------------------------------------------------------------------
// bf16 3-term GEMM core: C[128x128] block, 8 warps (2m x 4n), warp 64m x 32n.
// ---------------------------------------------------------------------------
__device__ __forceinline__ void gemm_core(const __nv_bfloat16* __restrict__ aH,
                                          const __nv_bfloat16* __restrict__ aL,
                                          const __nv_bfloat16* __restrict__ wH,
                                          const __nv_bfloat16* __restrict__ wL,
                                          const float* __restrict__ bias,
                                          int mode, int z, float* __restrict__ outF) {
    extern __shared__ __nv_bfloat16 sb[];
    const int t = threadIdx.x, lane = t & 31, warp = t >> 5;
    const int g = lane >> 2, c4 = lane & 3;
    const int wm = warp >> 2, wn = warp & 3;
    const int m0 = blockIdx.y * 128, n0 = blockIdx.x * 128;
    const uint32_t smem_u32 = (uint32_t)__cvta_generic_to_shared(sb);

    const __nv_bfloat16* ptrs[4] = { aH + (size_t)m0 * DM, aL + (size_t)m0 * DM,
                                     wH + (size_t)n0 * DM, wL + (size_t)n0 * DM };

    float c[4][4][4];
#pragma unroll
    for (int a = 0; a < 4; a++)
#pragma unroll
        for (int b = 0; b < 4; b++)
#pragma unroll
            for (int e = 0; e < 4; e++) c[a][b][e] = 0.f;

    auto issue = [&](int buf, int kc0) {
#pragma unroll
        for (int arr = 0; arr < 4; arr++)
#pragma unroll
            for (int i = 0; i < 2; i++) {
                int ch = t * 2 + i;
                int row = ch >> 2, seg = ch & 3;
                const void* src = ptrs[arr] + (size_t)row * DM + kc0 + seg * 8;
                uint32_t dst = smem_u32 + ((buf * 4 + arr) * 5120 + row * 40 + seg * 8) * 2;
                cpa16(dst, src);
            }
    };

    issue(0, 0);
    cp_commit();

    for (int it = 0; it < 16; ++it) {
        if (it < 15) { issue((it + 1) & 1, (it + 1) * 32); cp_commit(); cp_wait1(); }
        else cp_wait0();
        __syncthreads();

        const __nv_bfloat16* Ah = sb + ((it & 1) * 4 + 0) * 5120;
        const __nv_bfloat16* Al = sb + ((it & 1) * 4 + 1) * 5120;
        const __nv_bfloat16* Bh = sb + ((it & 1) * 4 + 2) * 5120;
        const __nv_bfloat16* Bl = sb + ((it & 1) * 4 + 3) * 5120;

#pragma unroll
        for (int ks = 0; ks < 2; ++ks) {
            uint32_t ah[4][4], al[4][4];
#pragma unroll
            for (int mt = 0; mt < 4; ++mt) {
                int r0 = wm * 64 + mt * 16 + g;
                const __nv_bfloat16* p = Ah + r0 * 40 + ks * 16 + c4 * 2;
                ah[mt][0] = ld32(p);
                ah[mt][1] = ld32(p + 8 * 40);
                ah[mt][2] = ld32(p + 8);
                ah[mt][3] = ld32(p + 8 * 40 + 8);
                const __nv_bfloat16* q = Al + r0 * 40 + ks * 16 + c4 * 2;
                al[mt][0] = ld32(q);
                al[mt][1] = ld32(q + 8 * 40);
                al[mt][2] = ld32(q + 8);
                al[mt][3] = ld32(q + 8 * 40 + 8);
            }
#pragma unroll
            for (int nt = 0; nt < 4; ++nt) {
                int rn = wn * 32 + nt * 8 + g;
                const __nv_bfloat16* pb = Bh + rn * 40 + ks * 16 + c4 * 2;
                uint32_t b0h = ld32(pb), b1h = ld32(pb + 8);
                const __nv_bfloat16* pl = Bl + rn * 40 + ks * 16 + c4 * 2;
                uint32_t b0l = ld32(pl), b1l = ld32(pl + 8);
#pragma unroll
                for (int mt = 0; mt < 4; ++mt) {
                    mma_bf16(c[mt][nt], ah[mt][0], ah[mt][1], ah[mt][2], ah[mt][3], b0h, b1h);
                    mma_bf16(c[mt][nt], ah[mt][0], ah[mt][1], ah[mt][2], ah[mt][3], b0l, b1l);
                    mma_bf16(c[mt][nt], al[mt][0], al[mt][1], al[mt][2], al[mt][3], b0h, b1h);
                }
            }
        }
        __syncthreads();
    }

    // epilogue
    __nv_bfloat16* dh = z == 0 ? g_q_hi : z == 1 ? g_k_hi : g_v_hi;
    __nv_bfloat16* dl = z == 0 ? g_q_lo : z == 1 ? g_k_lo : g_v_lo;
#pragma unroll
    for (int mt = 0; mt < 4; ++mt) {
        int mA = m0 + wm * 64 + mt * 16 + g;
#pragma unroll
        for (int nt = 0; nt < 4; ++nt) {
            int n = n0 + wn * 32 + nt * 8 + c4 * 2;
            float b0 = bias[n], b1 = bias[n + 1];
            float v00 = c[mt][nt][0] + b0, v01 = c[mt][nt][1] + b1;
            float v10 = c[mt][nt][2] + b0, v11 = c[mt][nt][3] + b1;
            if (mode == 0) {
                if (z == 0) { v00 *= 0.125f; v01 *= 0.125f; v10 *= 0.125f; v11 *= 0.125f; }
                int b_ = mA >> 12, s_ = mA & (NS - 1), h_ = n >> 6, d_ = n & 63;
                size_t idx = ((size_t)(b_ * NH + h_) * NS + s_) * DH + d_;
                uint32_t hi, lo;
                split_pack(v00, v01, hi, lo);
                *(uint32_t*)&dh[idx] = hi;
                *(uint32_t*)&dl[idx] = lo;
                split_pack(v10, v11, hi, lo);
                *(uint32_t*)&dh[idx + 8 * DH] = hi;
                *(uint32_t*)&dl[idx + 8 * DH] = lo;
            } else {
                outF[(size_t)mA * DM + n] = v00;
                outF[(size_t)mA * DM + n + 1] = v01;
                outF[(size_t)(mA + 8) * DM + n] = v10;
                outF[(size_t)(mA + 8) * DM + n + 1] = v11;
            }
        }
    }
}

__global__ __launch_bounds__(256, 2) void gemm_qkv_kernel(const float* __restrict__ bq,
                                                          const float* __restrict__ bk,
                                                          const float* __restrict__ bv) {
    const int z = blockIdx.z;
    const float* bias = z == 0 ? bq : z == 1 ? bk : bv;
    gemm_core(g_x_hi + (size_t)z * MK, g_x_lo + (size_t)z * MK,
              g_w_hi + (size_t)z * DM * DM, g_w_lo + (size_t)z * DM * DM,
              bias, 0, z, nullptr);
}

__global__ __launch_bounds__(256, 2) void gemm_out_kernel(const float* __restrict__ bo,
                                                          float* __restrict__ out) {
    gemm_core(g_a_hi, g_a_lo, g_w_hi + (size_t)3 * DM * DM, g_w_lo + (size_t)3 * DM * DM,
              bo, 1, 0, out);
}

// ---------------------------------------------------------------------------
// Flash attention, bf16 3-term mma. Q tile 128 (8 warps x 16 rows), K tile 64.
// Q hi/lo lives in SMEM (pitch-72, conflict-free) to cut register pressure ->
// 2 CTAs/SM. P reused as A fragments directly. V via ldmatrix.x4.trans.
// smem: KV ring 2 bufs x {Kh,Kl,Vh,Vl} x 64 x 72 (73728 B) + Q hi/lo 128 x 72
// (36864 B) = 110592 B.
// ---------------------------------------------------------------------------
__global__ __launch_bounds__(256, 2) void attn_kernel() {
    extern __shared__ __nv_bfloat16 sb[];
    const int t = threadIdx.x, lane = t & 31, warp = t >> 5;
    const int g = lane >> 2, c4 = lane & 3;
    const int bh = blockIdx.y;
    const int qr0 = blockIdx.x * 128;
    const int qr = qr0 + warp * 16;
    const uint32_t smem_u32 = (uint32_t)__cvta_generic_to_shared(sb);
    const size_t bho = (size_t)bh * NS * DH;

    __nv_bfloat16* Qh = sb + 8 * 4608;          // after KV ring
    __nv_bfloat16* Ql = Qh + 128 * 72;

    const __nv_bfloat16* srcs[4] = { g_k_hi + bho, g_k_lo + bho, g_v_hi + bho, g_v_lo + bho };

    // Q tile -> smem via cp.async (pitch 72)
    {
        const uint32_t qh_u = smem_u32 + (8 * 4608) * 2;
        const uint32_t ql_u = qh_u + 128 * 72 * 2;
#pragma unroll
        for (int i = 0; i < 4; i++) {
            int ch = t * 4 + i;                  // 0..1023
            int row = ch >> 3, seg = ch & 7;
            cpa16(qh_u + (row * 72 + seg * 8) * 2, g_q_hi + bho + (size_t)(qr0 + row) * DH + seg * 8);
            cpa16(ql_u + (row * 72 + seg * 8) * 2, g_q_lo + bho + (size_t)(qr0 + row) * DH + seg * 8);
        }
    }

    float o[8][4];
#pragma unroll
    for (int i = 0; i < 8; i++)
#pragma unroll
        for (int e = 0; e < 4; e++) o[i][e] = 0.f;
    float m0 = -1e30f, m1 = -1e30f, l0 = 0.f, l1 = 0.f;

    auto issue = [&](int buf, int kt) {
        const int k0 = kt * 64;
#pragma unroll
        for (int arr = 0; arr < 4; arr++)
#pragma unroll
            for (int i = 0; i < 2; i++) {
                int ch = t * 2 + i;              // 0..511
                int row = ch >> 3, seg = ch & 7;
                const void* src = srcs[arr] + (size_t)(k0 + row) * DH + seg * 8;
                uint32_t dst = smem_u32 + ((buf * 4 + arr) * 4608 + row * 72 + seg * 8) * 2;
                cpa16(dst, src);
            }
    };

    issue(0, 0);
    cp_commit();                                 // group: Q tile + KV tile 0

    for (int kt = 0; kt < NS / 64; ++kt) {
        if (kt < NS / 64 - 1) { issue((kt + 1) & 1, kt + 1); cp_commit(); cp_wait1(); }
        else cp_wait0();
        __syncthreads();

        const int bb = kt & 1;
        const __nv_bfloat16* Kh = sb + (bb * 4 + 0) * 4608;
        const __nv_bfloat16* Kl = sb + (bb * 4 + 1) * 4608;
        const uint32_t vh_base = smem_u32 + ((bb * 4 + 2) * 4608) * 2;
        const uint32_t vl_base = smem_u32 + ((bb * 4 + 3) * 4608) * 2;

        // S = Q K^T (Q a-frags re-read from smem each k-step)
        float s[8][4];
#pragma unroll
        for (int i = 0; i < 8; i++)
#pragma unroll
            for (int e = 0; e < 4; e++) s[i][e] = 0.f;

#pragma unroll
        for (int ks = 0; ks < 4; ++ks) {
            const __nv_bfloat16* ph = Qh + (qr - qr0 + g) * 72 + ks * 16 + c4 * 2;
            uint32_t ah0 = ld32(ph), ah1 = ld32(ph + 8 * 72), ah2 = ld32(ph + 8), ah3 = ld32(ph + 8 * 72 + 8);
            const __nv_bfloat16* pl = Ql + (qr - qr0 + g) * 72 + ks * 16 + c4 * 2;
            uint32_t al0 = ld32(pl), al1 = ld32(pl + 8 * 72), al2 = ld32(pl + 8), al3 = ld32(pl + 8 * 72 + 8);
#pragma unroll
            for (int nt = 0; nt < 8; ++nt) {
                int j = nt * 8 + g;
                const __nv_bfloat16* pb = Kh + j * 72 + ks * 16 + c4 * 2;
                uint32_t b0h = ld32(pb), b1h = ld32(pb + 8);
                const __nv_bfloat16* pbl = Kl + j * 72 + ks * 16 + c4 * 2;
                uint32_t b0l = ld32(pbl), b1l = ld32(pbl + 8);
                mma_bf16(s[nt], ah0, ah1, ah2, ah3, b0h, b1h);
                mma_bf16(s[nt], ah0, ah1, ah2, ah3, b0l, b1l);
                mma_bf16(s[nt], al0, al1, al2, al3, b0h, b1h);
            }
        }

        // online softmax (rows g and g+8)
        float mx0 = -1e30f, mx1 = -1e30f;
#pragma unroll
        for (int nt = 0; nt < 8; ++nt) {
            mx0 = fmaxf(mx0, fmaxf(s[nt][0], s[nt][1]));
            mx1 = fmaxf(mx1, fmaxf(s[nt][2], s[nt][3]));
        }
        mx0 = fmaxf(mx0, __shfl_xor_sync(0xffffffffu, mx0, 1));
        mx0 = fmaxf(mx0, __shfl_xor_sync(0xffffffffu, mx0, 2));
        mx1 = fmaxf(mx1, __shfl_xor_sync(0xffffffffu, mx1, 1));
        mx1 = fmaxf(mx1, __shfl_xor_sync(0xffffffffu, mx1, 2));
        float mn0 = fmaxf(m0, mx0), mn1 = fmaxf(m1, mx1);
        float cr0 = __expf(m0 - mn0), cr1 = __expf(m1 - mn1);
        m0 = mn0; m1 = mn1;
        float sum0 = 0.f, sum1 = 0.f;
#pragma unroll
        for (int nt = 0; nt < 8; ++nt) {
            s[nt][0] = __expf(s[nt][0] - mn0); sum0 += s[nt][0];
            s[nt][1] = __expf(s[nt][1] - mn0); sum0 += s[nt][1];
            s[nt][2] = __expf(s[nt][2] - mn1); sum1 += s[nt][2];
            s[nt][3] = __expf(s[nt][3] - mn1); sum1 += s[nt][3];
        }
        sum0 += __shfl_xor_sync(0xffffffffu, sum0, 1);
        sum0 += __shfl_xor_sync(0xffffffffu, sum0, 2);
        sum1 += __shfl_xor_sync(0xffffffffu, sum1, 1);
        sum1 += __shfl_xor_sync(0xffffffffu, sum1, 2);
        l0 = l0 * cr0 + sum0;
        l1 = l1 * cr1 + sum1;
#pragma unroll
        for (int nt = 0; nt < 8; ++nt) {
            o[nt][0] *= cr0; o[nt][1] *= cr0; o[nt][2] *= cr1; o[nt][3] *= cr1;
        }

        // O += P V (P from s fragments, split on the fly)
#pragma unroll
        for (int tk = 0; tk < 4; ++tk) {
            uint32_t ah[4], al[4];
            split_pack(s[2 * tk][0],     s[2 * tk][1],     ah[0], al[0]);
            split_pack(s[2 * tk][2],     s[2 * tk][3],     ah[1], al[1]);
            split_pack(s[2 * tk + 1][0], s[2 * tk + 1][1], ah[2], al[2]);
            split_pack(s[2 * tk + 1][2], s[2 * tk + 1][3], ah[3], al[3]);
            int jrow = tk * 16 + (lane & 15);
            int coff = (lane >> 4) * 8;
#pragma unroll
            for (int np = 0; np < 4; ++np) {
                uint32_t vh[4], vl[4];
                ldm4t(vh, vh_base + (jrow * 72 + np * 16 + coff) * 2);
                ldm4t(vl, vl_base + (jrow * 72 + np * 16 + coff) * 2);
                mma_bf16(o[np * 2],     ah[0], ah[1], ah[2], ah[3], vh[0], vh[1]);
                mma_bf16(o[np * 2],     ah[0], ah[1], ah[2], ah[3], vl[0], vl[1]);
                mma_bf16(o[np * 2],     al[0], al[1], al[2], al[3], vh[0], vh[1]);
                mma_bf16(o[np * 2 + 1], ah[0], ah[1], ah[2], ah[3], vh[2], vh[3]);
                mma_bf16(o[np * 2 + 1], ah[0], ah[1], ah[2], ah[3], vl[2], vl[3]);
                mma_bf16(o[np * 2 + 1], al[0], al[1], al[2], al[3], vh[2], vh[3]);
            }
        }
        __syncthreads();
    }

    // epilogue: normalize, split, write [s][dm] bf16 hi/lo
    float inv0 = 1.f / l0, inv1 = 1.f / l1;
    const int b_ = bh >> 3, h_ = bh & 7;
    size_t r0 = (size_t)(b_ * NS + qr + g) * DM + h_ * 64;
    size_t r1 = r0 + (size_t)8 * DM;
#pragma unroll
    for (int nt = 0; nt < 8; ++nt) {
        uint32_t hi, lo;
        int d = nt * 8 + c4 * 2;
        split_pack(o[nt][0] * inv0, o[nt][1] * inv0, hi, lo);
        *(uint32_t*)&g_a_hi[r0 + d] = hi;
        *(uint32_t*)&g_a_lo[r0 + d] = lo;
        split_pack(o[nt][2] * inv1, o[nt][3] * inv1, hi, lo);
        *(uint32_t*)&g_a_hi[r1 + d] = hi;
        *(uint32_t*)&g_a_lo[r1 + d] = lo;
    }
}

// ---------------------------------------------------------------------------
extern "C" void kernel_launch(void* const* d_in, const int* in_sizes, int n_in,
                              void* d_out, int out_size) {
    const float* q  = (const float*)d_in[0];
    const float* k  = (const float*)d_in[1];
    const float* v  = (const float*)d_in[2];
    const float* wq = (const float*)d_in[3];
    const float* bq = (const float*)d_in[4];
    const float* wk = (const float*)d_in[5];
    const float* bk = (const float*)d_in[6];
    const float* wv = (const float*)d_in[7];
    const float* bv = (const float*)d_in[8];
    const float* wo = (const float*)d_in[9];
    const float* bo = (const float*)d_in[10];
    float* out = (float*)d_out;

    const int smem_gemm = 2 * 4 * 128 * 40 * 2;                  // 81920
    const int smem_attn = (8 * 4608 + 2 * 128 * 72) * 2;         // 110592
    cudaFuncSetAttribute(gemm_qkv_kernel, cudaFuncAttributeMaxDynamicSharedMemorySize, smem_gemm);
    cudaFuncSetAttribute(gemm_out_kernel, cudaFuncAttributeMaxDynamicSharedMemorySize, smem_gemm);
    cudaFuncSetAttribute(attn_kernel,     cudaFuncAttributeMaxDynamicSharedMemorySize, smem_attn);

    wsplit_kernel<<<dim3(16, 16, 4), dim3(32, 8)>>>(wq, wk, wv, wo);
    xsplit_kernel<<<dim3(MK / 1024, 3), 256>>>(q, k, v);
    gemm_qkv_kernel<<<dim3(4, 64, 3), 256, smem_gemm>>>(bq, bk, bv);
    attn_kernel<<<dim3(32, 16), 256, smem_attn>>>();
    gemm_out_kernel<<<dim3(4, 64), 256, smem_gemm>>>(bo, out);
}

// round 5
// speedup vs baseline: 2.9028x; 1.0505x over previous
#include <cuda_runtime.h>
#include <cuda_bf16.h>
#include <stdint.h>
#include <math.h>

#define NB 2
#define NS 4096
#define DM 512
#define NH 8
#define DH 64
#define MTOT (NB * NS)          // 8192
#define MK   (MTOT * DM)        // 4194304

// ---------------------------------------------------------------------------
// Device-global scratch. bf16 hi/lo split pairs.
// ---------------------------------------------------------------------------
__device__ __align__(256) __nv_bfloat16 g_x_hi[3 * MK], g_x_lo[3 * MK];           // split q/k/v inputs
__device__ __align__(256) __nv_bfloat16 g_w_hi[4 * DM * DM], g_w_lo[4 * DM * DM]; // wT [z][n][k]
__device__ __align__(256) __nv_bfloat16 g_q_hi[MK], g_q_lo[MK];                   // [bh][s][dh], pre-scaled 0.125*log2e
__device__ __align__(256) __nv_bfloat16 g_k_hi[MK], g_k_lo[MK];                   // [bh][s][dh]
__device__ __align__(256) __nv_bfloat16 g_v_hi[MK], g_v_lo[MK];                   // [bh][s][dh]
__device__ __align__(256) __nv_bfloat16 g_a_hi[MK], g_a_lo[MK];                   // attn out [s][dm]

// ---------------------------------------------------------------------------
// PTX helpers
// ---------------------------------------------------------------------------
__device__ __forceinline__ void mma_bf16(float* c, uint32_t a0, uint32_t a1,
                                         uint32_t a2, uint32_t a3,
                                         uint32_t b0, uint32_t b1) {
    asm volatile(
        "mma.sync.aligned.m16n8k16.row.col.f32.bf16.bf16.f32 "
        "{%0,%1,%2,%3},{%4,%5,%6,%7},{%8,%9},{%0,%1,%2,%3};"
        : "+f"(c[0]), "+f"(c[1]), "+f"(c[2]), "+f"(c[3])
        : "r"(a0), "r"(a1), "r"(a2), "r"(a3), "r"(b0), "r"(b1));
}

__device__ __forceinline__ void ldm4(uint32_t* r, uint32_t addr) {
    asm volatile(
        "ldmatrix.sync.aligned.m8n8.x4.shared.b16 {%0,%1,%2,%3},[%4];"
        : "=r"(r[0]), "=r"(r[1]), "=r"(r[2]), "=r"(r[3]) : "r"(addr));
}
__device__ __forceinline__ void ldm4t(uint32_t* r, uint32_t addr) {
    asm volatile(
        "ldmatrix.sync.aligned.m8n8.x4.trans.shared.b16 {%0,%1,%2,%3},[%4];"
        : "=r"(r[0]), "=r"(r[1]), "=r"(r[2]), "=r"(r[3]) : "r"(addr));
}

__device__ __forceinline__ void cpa16(uint32_t dst, const void* src) {
    asm volatile("cp.async.cg.shared.global [%0], [%1], 16;\n" :: "r"(dst), "l"(src));
}
__device__ __forceinline__ void cp_commit() { asm volatile("cp.async.commit_group;\n"); }
__device__ __forceinline__ void cp_wait0() { asm volatile("cp.async.wait_group 0;\n"); }
__device__ __forceinline__ void cp_wait1() { asm volatile("cp.async.wait_group 1;\n"); }

__device__ __forceinline__ float ex2f(float x) {
    float y;
    asm("ex2.approx.f32 %0, %1;" : "=f"(y) : "f"(x));
    return y;
}

// split x into bf16 hi + bf16 lo (2-term compensated decomposition)
__device__ __forceinline__ void split1(float x, __nv_bfloat16& h, __nv_bfloat16& l) {
    h = __float2bfloat16(x);
    l = __float2bfloat16(x - __bfloat162float(h));
}
__device__ __forceinline__ void split_pack(float e0, float e1, uint32_t& hi, uint32_t& lo) {
    __nv_bfloat16 h0, l0, h1, l1;
    split1(e0, h0, l0);
    split1(e1, h1, l1);
    hi = (uint32_t)*(unsigned short*)&h0 | ((uint32_t)*(unsigned short*)&h1 << 16);
    lo = (uint32_t)*(unsigned short*)&l0 | ((uint32_t)*(unsigned short*)&l1 << 16);
}

// ---------------------------------------------------------------------------
// Weight transpose + split: w[k][n] fp32 -> wT_hi/lo[n][k] bf16
// ---------------------------------------------------------------------------
__global__ void wsplit_kernel(const float* __restrict__ wq, const float* __restrict__ wk,
                              const float* __restrict__ wv, const float* __restrict__ wo) {
    __shared__ float tl[32][33];
    const float* w = blockIdx.z == 0 ? wq : blockIdx.z == 1 ? wk : blockIdx.z == 2 ? wv : wo;
    const int n0 = blockIdx.x * 32, k0 = blockIdx.y * 32;
    const int tx = threadIdx.x, ty = threadIdx.y;  // 32 x 8
#pragma unroll
    for (int i = 0; i < 32; i += 8)
        tl[ty + i][tx] = w[(size_t)(k0 + ty + i) * DM + n0 + tx];
    __syncthreads();
#pragma unroll
    for (int i = 0; i < 32; i += 8) {
        float v = tl[tx][ty + i];
        __nv_bfloat16 h, l;
        split1(v, h, l);
        size_t idx = (size_t)blockIdx.z * DM * DM + (size_t)(n0 + ty + i) * DM + k0 + tx;
        g_w_hi[idx] = h;
        g_w_lo[idx] = l;
    }
}

// ---------------------------------------------------------------------------
// Input split: q/k/v fp32 [m][k] -> g_x_hi/lo, float4-vectorized
// ---------------------------------------------------------------------------
__global__ void xsplit_kernel(const float* __restrict__ q, const float* __restrict__ k,
                              const float* __restrict__ v) {
    const int z = blockIdx.y;
    const float* src = z == 0 ? q : z == 1 ? k : v;
    int i = (blockIdx.x * 256 + threadIdx.x) * 4;
    float4 x4 = *(const float4*)(src + i);
    uint32_t h01, l01, h23, l23;
    split_pack(x4.x, x4.y, h01, l01);
    split_pack(x4.z, x4.w, h23, l23);
    uint2 hh = make_uint2(h01, h23), ll = make_uint2(l01, l23);
    *(uint2*)&g_x_hi[(size_t)z * MK + i] = hh;
    *(uint2*)&g_x_lo[(size_t)z * MK + i] = ll;
}

// ---------------------------------------------------------------------------
// bf16 3-term GEMM core: C[128x128] block, 8 warps (2m x 4n), warp 64m x 32n.
// Fragments via ldmatrix.x4.
// ---------------------------------------------------------------------------
__device__ __forceinline__ void gemm_core(const __nv_bfloat16* __restrict__ aH,
                                          const __nv_bfloat16* __restrict__ aL,
                                          const __nv_bfloat16* __restrict__ wH,
                                          const __nv_bfloat16* __restrict__ wL,
                                          const float* __restrict__ bias,
                                          int mode, int z, float* __restrict__ outF) {
    extern __shared__ __align__(16) __nv_bfloat16 sb[];
    const int t = threadIdx.x, lane = t & 31, warp = t >> 5;
    const int g = lane >> 2, c4 = lane & 3;
    const int wm = warp >> 2, wn = warp & 3;
    const int m0 = blockIdx.y * 128, n0 = blockIdx.x * 128;
    const uint32_t smem_u32 = (uint32_t)__cvta_generic_to_shared(sb);

    // ldmatrix lane-dependent byte offsets (pitch 40 elems = 80 B)
    const uint32_t a_ln = (uint32_t)(((lane & 7) + ((lane >> 3) & 1) * 8) * 80 + (lane >> 4) * 16);
    const uint32_t b_ln = (uint32_t)(((lane >> 4) * 8 + (lane & 7)) * 80 + ((lane >> 3) & 1) * 16);

    const __nv_bfloat16* ptrs[4] = { aH + (size_t)m0 * DM, aL + (size_t)m0 * DM,
                                     wH + (size_t)n0 * DM, wL + (size_t)n0 * DM };

    float c[4][4][4];
#pragma unroll
    for (int a = 0; a < 4; a++)
#pragma unroll
        for (int b = 0; b < 4; b++)
#pragma unroll
            for (int e = 0; e < 4; e++) c[a][b][e] = 0.f;

    auto issue = [&](int buf, int kc0) {
#pragma unroll
        for (int arr = 0; arr < 4; arr++)
#pragma unroll
            for (int i = 0; i < 2; i++) {
                int ch = t * 2 + i;
                int row = ch >> 2, seg = ch & 3;
                const void* src = ptrs[arr] + (size_t)row * DM + kc0 + seg * 8;
                uint32_t dst = smem_u32 + ((buf * 4 + arr) * 5120 + row * 40 + seg * 8) * 2;
                cpa16(dst, src);
            }
    };

    issue(0, 0);
    cp_commit();

    for (int it = 0; it < 16; ++it) {
        if (it < 15) { issue((it + 1) & 1, (it + 1) * 32); cp_commit(); cp_wait1(); }
        else cp_wait0();
        __syncthreads();

        const uint32_t Ah_u = smem_u32 + ((it & 1) * 4 + 0) * 5120 * 2;
        const uint32_t Al_u = smem_u32 + ((it & 1) * 4 + 1) * 5120 * 2;
        const uint32_t Bh_u = smem_u32 + ((it & 1) * 4 + 2) * 5120 * 2;
        const uint32_t Bl_u = smem_u32 + ((it & 1) * 4 + 3) * 5120 * 2;

#pragma unroll
        for (int ks = 0; ks < 2; ++ks) {
            uint32_t ah[4][4], al[4][4];
#pragma unroll
            for (int mt = 0; mt < 4; ++mt) {
                uint32_t ro = (uint32_t)((wm * 64 + mt * 16) * 80 + ks * 32) + a_ln;
                ldm4(ah[mt], Ah_u + ro);
                ldm4(al[mt], Al_u + ro);
            }
#pragma unroll
            for (int p = 0; p < 2; ++p) {
                uint32_t ro = (uint32_t)((wn * 32 + p * 16) * 80 + ks * 32) + b_ln;
                uint32_t bh[4], bl[4];
                ldm4(bh, Bh_u + ro);
                ldm4(bl, Bl_u + ro);
#pragma unroll
                for (int mt = 0; mt < 4; ++mt) {
                    mma_bf16(c[mt][2 * p], ah[mt][0], ah[mt][1], ah[mt][2], ah[mt][3], bh[0], bh[1]);
                    mma_bf16(c[mt][2 * p], ah[mt][0], ah[mt][1], ah[mt][2], ah[mt][3], bl[0], bl[1]);
                    mma_bf16(c[mt][2 * p], al[mt][0], al[mt][1], al[mt][2], al[mt][3], bh[0], bh[1]);
                    mma_bf16(c[mt][2 * p + 1], ah[mt][0], ah[mt][1], ah[mt][2], ah[mt][3], bh[2], bh[3]);
                    mma_bf16(c[mt][2 * p + 1], ah[mt][0], ah[mt][1], ah[mt][2], ah[mt][3], bl[2], bl[3]);
                    mma_bf16(c[mt][2 * p + 1], al[mt][0], al[mt][1], al[mt][2], al[mt][3], bh[2], bh[3]);
                }
            }
        }
        __syncthreads();
    }

    // epilogue
    __nv_bfloat16* dh = z == 0 ? g_q_hi : z == 1 ? g_k_hi : g_v_hi;
    __nv_bfloat16* dl = z == 0 ? g_q_lo : z == 1 ? g_k_lo : g_v_lo;
    const float qscale = 0.125f * 1.44269504f;   // 1/sqrt(dh) * log2(e)
#pragma unroll
    for (int mt = 0; mt < 4; ++mt) {
        int mA = m0 + wm * 64 + mt * 16 + g;
#pragma unroll
        for (int nt = 0; nt < 4; ++nt) {
            int n = n0 + wn * 32 + nt * 8 + c4 * 2;
            float b0 = bias[n], b1 = bias[n + 1];
            float v00 = c[mt][nt][0] + b0, v01 = c[mt][nt][1] + b1;
            float v10 = c[mt][nt][2] + b0, v11 = c[mt][nt][3] + b1;
            if (mode == 0) {
                if (z == 0) { v00 *= qscale; v01 *= qscale; v10 *= qscale; v11 *= qscale; }
                int b_ = mA >> 12, s_ = mA & (NS - 1), h_ = n >> 6, d_ = n & 63;
                size_t idx = ((size_t)(b_ * NH + h_) * NS + s_) * DH + d_;
                uint32_t hi, lo;
                split_pack(v00, v01, hi, lo);
                *(uint32_t*)&dh[idx] = hi;
                *(uint32_t*)&dl[idx] = lo;
                split_pack(v10, v11, hi, lo);
                *(uint32_t*)&dh[idx + 8 * DH] = hi;
                *(uint32_t*)&dl[idx + 8 * DH] = lo;
            } else {
                outF[(size_t)mA * DM + n] = v00;
                outF[(size_t)mA * DM + n + 1] = v01;
                outF[(size_t)(mA + 8) * DM + n] = v10;
                outF[(size_t)(mA + 8) * DM + n + 1] = v11;
            }
        }
    }
}

__global__ __launch_bounds__(256, 2) void gemm_qkv_kernel(const float* __restrict__ bq,
                                                          const float* __restrict__ bk,
                                                          const float* __restrict__ bv) {
    const int z = blockIdx.z;
    const float* bias = z == 0 ? bq : z == 1 ? bk : bv;
    gemm_core(g_x_hi + (size_t)z * MK, g_x_lo + (size_t)z * MK,
              g_w_hi + (size_t)z * DM * DM, g_w_lo + (size_t)z * DM * DM,
              bias, 0, z, nullptr);
}

__global__ __launch_bounds__(256, 2) void gemm_out_kernel(const float* __restrict__ bo,
                                                          float* __restrict__ out) {
    gemm_core(g_a_hi, g_a_lo, g_w_hi + (size_t)3 * DM * DM, g_w_lo + (size_t)3 * DM * DM,
              bo, 1, 0, out);
}

// ---------------------------------------------------------------------------
// Flash attention, bf16 3-term mma, all fragments via ldmatrix.
// Q tile 128 (8 warps x 16 rows) in smem, K tile 64 double-buffered.
// smem: KV ring 2 x {Kh,Kl,Vh,Vl} x 64x72 (73728 B) + Q hi/lo 128x72 (36864 B).
// ---------------------------------------------------------------------------
__global__ __launch_bounds__(256, 2) void attn_kernel() {
    extern __shared__ __align__(16) __nv_bfloat16 sb[];
    const int t = threadIdx.x, lane = t & 31, warp = t >> 5;
    const int g = lane >> 2, c4 = lane & 3;
    const int bh = blockIdx.y;
    const int qr0 = blockIdx.x * 128;
    const int qr = qr0 + warp * 16;
    const int qloc = warp * 16;
    const uint32_t smem_u32 = (uint32_t)__cvta_generic_to_shared(sb);
    const size_t bho = (size_t)bh * NS * DH;

    const uint32_t qh_u = smem_u32 + (8 * 4608) * 2;
    const uint32_t ql_u = qh_u + 128 * 72 * 2;

    // ldmatrix lane-dependent byte offsets (pitch 72 elems = 144 B)
    const uint32_t a_ln = (uint32_t)(((lane & 7) + ((lane >> 3) & 1) * 8) * 144 + (lane >> 4) * 16);
    const uint32_t b_ln = (uint32_t)(((lane >> 4) * 8 + (lane & 7)) * 144 + ((lane >> 3) & 1) * 16);

    const __nv_bfloat16* srcs[4] = { g_k_hi + bho, g_k_lo + bho, g_v_hi + bho, g_v_lo + bho };

    // Q tile -> smem via cp.async (pitch 72)
    {
#pragma unroll
        for (int i = 0; i < 4; i++) {
            int ch = t * 4 + i;                  // 0..1023
            int row = ch >> 3, seg = ch & 7;
            cpa16(qh_u + (row * 72 + seg * 8) * 2, g_q_hi + bho + (size_t)(qr0 + row) * DH + seg * 8);
            cpa16(ql_u + (row * 72 + seg * 8) * 2, g_q_lo + bho + (size_t)(qr0 + row) * DH + seg * 8);
        }
    }

    float o[8][4];
#pragma unroll
    for (int i = 0; i < 8; i++)
#pragma unroll
        for (int e = 0; e < 4; e++) o[i][e] = 0.f;
    float m0 = -1e30f, m1 = -1e30f, l0 = 0.f, l1 = 0.f;

    auto issue = [&](int buf, int kt) {
        const int k0 = kt * 64;
#pragma unroll
        for (int arr = 0; arr < 4; arr++)
#pragma unroll
            for (int i = 0; i < 2; i++) {
                int ch = t * 2 + i;              // 0..511
                int row = ch >> 3, seg = ch & 7;
                const void* src = srcs[arr] + (size_t)(k0 + row) * DH + seg * 8;
                uint32_t dst = smem_u32 + ((buf * 4 + arr) * 4608 + row * 72 + seg * 8) * 2;
                cpa16(dst, src);
            }
    };

    issue(0, 0);
    cp_commit();                                 // group: Q tile + KV tile 0

    for (int kt = 0; kt < NS / 64; ++kt) {
        if (kt < NS / 64 - 1) { issue((kt + 1) & 1, kt + 1); cp_commit(); cp_wait1(); }
        else cp_wait0();
        __syncthreads();

        const int bb = kt & 1;
        const uint32_t kh_u = smem_u32 + ((bb * 4 + 0) * 4608) * 2;
        const uint32_t kl_u = smem_u32 + ((bb * 4 + 1) * 4608) * 2;
        const uint32_t vh_u = smem_u32 + ((bb * 4 + 2) * 4608) * 2;
        const uint32_t vl_u = smem_u32 + ((bb * 4 + 3) * 4608) * 2;

        // S = Q K^T, fragments via ldmatrix.x4
        float s[8][4];
#pragma unroll
        for (int i = 0; i < 8; i++)
#pragma unroll
            for (int e = 0; e < 4; e++) s[i][e] = 0.f;

#pragma unroll
        for (int ks = 0; ks < 4; ++ks) {
            uint32_t ah[4], al[4];
            uint32_t aro = (uint32_t)(qloc * 144 + ks * 32) + a_ln;
            ldm4(ah, qh_u + aro);
            ldm4(al, ql_u + aro);
#pragma unroll
            for (int p = 0; p < 4; ++p) {
                uint32_t bro = (uint32_t)(p * 16 * 144 + ks * 32) + b_ln;
                uint32_t bhr[4], blr[4];
                ldm4(bhr, kh_u + bro);
                ldm4(blr, kl_u + bro);
                mma_bf16(s[2 * p],     ah[0], ah[1], ah[2], ah[3], bhr[0], bhr[1]);
                mma_bf16(s[2 * p],     ah[0], ah[1], ah[2], ah[3], blr[0], blr[1]);
                mma_bf16(s[2 * p],     al[0], al[1], al[2], al[3], bhr[0], bhr[1]);
                mma_bf16(s[2 * p + 1], ah[0], ah[1], ah[2], ah[3], bhr[2], bhr[3]);
                mma_bf16(s[2 * p + 1], ah[0], ah[1], ah[2], ah[3], blr[2], blr[3]);
                mma_bf16(s[2 * p + 1], al[0], al[1], al[2], al[3], bhr[2], bhr[3]);
            }
        }

        // online softmax in log2 domain (rows g and g+8)
        float mx0 = -1e30f, mx1 = -1e30f;
#pragma unroll
        for (int nt = 0; nt < 8; ++nt) {
            mx0 = fmaxf(mx0, fmaxf(s[nt][0], s[nt][1]));
            mx1 = fmaxf(mx1, fmaxf(s[nt][2], s[nt][3]));
        }
        mx0 = fmaxf(mx0, __shfl_xor_sync(0xffffffffu, mx0, 1));
        mx0 = fmaxf(mx0, __shfl_xor_sync(0xffffffffu, mx0, 2));
        mx1 = fmaxf(mx1, __shfl_xor_sync(0xffffffffu, mx1, 1));
        mx1 = fmaxf(mx1, __shfl_xor_sync(0xffffffffu, mx1, 2));
        float mn0 = fmaxf(m0, mx0), mn1 = fmaxf(m1, mx1);
        float cr0 = ex2f(m0 - mn0), cr1 = ex2f(m1 - mn1);
        m0 = mn0; m1 = mn1;
        float sum0 = 0.f, sum1 = 0.f;
#pragma unroll
        for (int nt = 0; nt < 8; ++nt) {
            s[nt][0] = ex2f(s[nt][0] - mn0); sum0 += s[nt][0];
            s[nt][1] = ex2f(s[nt][1] - mn0); sum0 += s[nt][1];
            s[nt][2] = ex2f(s[nt][2] - mn1); sum1 += s[nt][2];
            s[nt][3] = ex2f(s[nt][3] - mn1); sum1 += s[nt][3];
        }
        sum0 += __shfl_xor_sync(0xffffffffu, sum0, 1);
        sum0 += __shfl_xor_sync(0xffffffffu, sum0, 2);
        sum1 += __shfl_xor_sync(0xffffffffu, sum1, 1);
        sum1 += __shfl_xor_sync(0xffffffffu, sum1, 2);
        l0 = l0 * cr0 + sum0;
        l1 = l1 * cr1 + sum1;
#pragma unroll
        for (int nt = 0; nt < 8; ++nt) {
            o[nt][0] *= cr0; o[nt][1] *= cr0; o[nt][2] *= cr1; o[nt][3] *= cr1;
        }

        // O += P V (P from s fragments, split on the fly; V via ldmatrix.trans)
#pragma unroll
        for (int tk = 0; tk < 4; ++tk) {
            uint32_t ah[4], al[4];
            split_pack(s[2 * tk][0],     s[2 * tk][1],     ah[0], al[0]);
            split_pack(s[2 * tk][2],     s[2 * tk][3],     ah[1], al[1]);
            split_pack(s[2 * tk + 1][0], s[2 * tk + 1][1], ah[2], al[2]);
            split_pack(s[2 * tk + 1][2], s[2 * tk + 1][3], ah[3], al[3]);
            int jrow = tk * 16 + (lane & 15);
            int coff = (lane >> 4) * 8;
#pragma unroll
            for (int np = 0; np < 4; ++np) {
                uint32_t vh[4], vl[4];
                ldm4t(vh, vh_u + (jrow * 72 + np * 16 + coff) * 2);
                ldm4t(vl, vl_u + (jrow * 72 + np * 16 + coff) * 2);
                mma_bf16(o[np * 2],     ah[0], ah[1], ah[2], ah[3], vh[0], vh[1]);
                mma_bf16(o[np * 2],     ah[0], ah[1], ah[2], ah[3], vl[0], vl[1]);
                mma_bf16(o[np * 2],     al[0], al[1], al[2], al[3], vh[0], vh[1]);
                mma_bf16(o[np * 2 + 1], ah[0], ah[1], ah[2], ah[3], vh[2], vh[3]);
                mma_bf16(o[np * 2 + 1], ah[0], ah[1], ah[2], ah[3], vl[2], vl[3]);
                mma_bf16(o[np * 2 + 1], al[0], al[1], al[2], al[3], vh[2], vh[3]);
            }
        }
        __syncthreads();
    }

    // epilogue: normalize, split, write [s][dm] bf16 hi/lo
    float inv0 = 1.f / l0, inv1 = 1.f / l1;
    const int b_ = bh >> 3, h_ = bh & 7;
    size_t r0 = (size_t)(b_ * NS + qr + g) * DM + h_ * 64;
    size_t r1 = r0 + (size_t)8 * DM;
#pragma unroll
    for (int nt = 0; nt < 8; ++nt) {
        uint32_t hi, lo;
        int d = nt * 8 + c4 * 2;
        split_pack(o[nt][0] * inv0, o[nt][1] * inv0, hi, lo);
        *(uint32_t*)&g_a_hi[r0 + d] = hi;
        *(uint32_t*)&g_a_lo[r0 + d] = lo;
        split_pack(o[nt][2] * inv1, o[nt][3] * inv1, hi, lo);
        *(uint32_t*)&g_a_hi[r1 + d] = hi;
        *(uint32_t*)&g_a_lo[r1 + d] = lo;
    }
}

// ---------------------------------------------------------------------------
extern "C" void kernel_launch(void* const* d_in, const int* in_sizes, int n_in,
                              void* d_out, int out_size) {
    const float* q  = (const float*)d_in[0];
    const float* k  = (const float*)d_in[1];
    const float* v  = (const float*)d_in[2];
    const float* wq = (const float*)d_in[3];
    const float* bq = (const float*)d_in[4];
    const float* wk = (const float*)d_in[5];
    const float* bk = (const float*)d_in[6];
    const float* wv = (const float*)d_in[7];
    const float* bv = (const float*)d_in[8];
    const float* wo = (const float*)d_in[9];
    const float* bo = (const float*)d_in[10];
    float* out = (float*)d_out;

    const int smem_gemm = 2 * 4 * 128 * 40 * 2;                  // 81920
    const int smem_attn = (8 * 4608 + 2 * 128 * 72) * 2;         // 110592
    cudaFuncSetAttribute(gemm_qkv_kernel, cudaFuncAttributeMaxDynamicSharedMemorySize, smem_gemm);
    cudaFuncSetAttribute(gemm_out_kernel, cudaFuncAttributeMaxDynamicSharedMemorySize, smem_gemm);
    cudaFuncSetAttribute(attn_kernel,     cudaFuncAttributeMaxDynamicSharedMemorySize, smem_attn);

    wsplit_kernel<<<dim3(16, 16, 4), dim3(32, 8)>>>(wq, wk, wv, wo);
    xsplit_kernel<<<dim3(MK / 1024, 3), 256>>>(q, k, v);
    gemm_qkv_kernel<<<dim3(4, 64, 3), 256, smem_gemm>>>(bq, bk, bv);
    attn_kernel<<<dim3(32, 16), 256, smem_attn>>>();
    gemm_out_kernel<<<dim3(4, 64), 256, smem_gemm>>>(bo, out);
}